// round 3
// baseline (speedup 1.0000x reference)
#include <cuda_runtime.h>
#include <math.h>

#define NSEG  125000
#define VROWS 1000000

// ---------------- scratch (device globals; no allocation allowed) ----------
static __device__ float g_z2[(size_t)VROWS * 64];   // z2 pre-BN activations
static __device__ float g_q [(size_t)NSEG * 64];    // per-segment query
static __device__ float g_Pt[(size_t)NSEG * 64];    // Wk_top @ q   (h2 part)
static __device__ float g_Pb[(size_t)NSEG * 128];   // Wk_bot @ q   (x_mod part)
static __device__ float g_c [NSEG];                 // bk . q
static __device__ float g_X [VROWS];                // per-row scores
static __device__ float g_stats1[128];              // sum(64) | sumsq(64)
static __device__ float g_stats2[128];
static __device__ float g_s1[64], g_t1[64], g_s2[64], g_t2[64];

// ---------------- init: zero the stat accumulators -------------------------
__global__ void k_init() {
    int t = threadIdx.x;
    if (t < 128) { g_stats1[t] = 0.f; g_stats2[t] = 0.f; }
}

// ---------------- pass 1: z1 = x_proj@W1+b1, accumulate BN1 stats ----------
__global__ void __launch_bounds__(256) k_stats1(const float* __restrict__ xp,
                                                const float* __restrict__ W1,
                                                const float* __restrict__ b1) {
    __shared__ float sW[2048];          // 32x64
    __shared__ float sSum[64], sSq[64];
    int t = threadIdx.x;
    for (int i = t; i < 2048; i += 256) sW[i] = W1[i];
    if (t < 64) { sSum[t] = 0.f; sSq[t] = 0.f; }
    __syncthreads();

    int v = blockIdx.x * 256 + t;
    bool valid = v < VROWS;
    float acc[64];
#pragma unroll
    for (int j = 0; j < 64; j++) acc[j] = __ldg(b1 + j);

    if (valid) {
        const float4* xr = reinterpret_cast<const float4*>(xp + (size_t)v * 32);
        for (int ko = 0; ko < 8; ko++) {          // rolled: small code
            float4 xv = __ldg(xr + ko);
            float xs[4] = {xv.x, xv.y, xv.z, xv.w};
#pragma unroll
            for (int kk = 0; kk < 4; kk++) {
                const float4* wr =
                    reinterpret_cast<const float4*>(sW + (ko * 4 + kk) * 64);
#pragma unroll
                for (int jo = 0; jo < 16; jo++) {
                    float4 w = wr[jo];
                    acc[jo*4+0] += xs[kk] * w.x;
                    acc[jo*4+1] += xs[kk] * w.y;
                    acc[jo*4+2] += xs[kk] * w.z;
                    acc[jo*4+3] += xs[kk] * w.w;
                }
            }
        }
    }

    const unsigned FULL = 0xffffffffu;
#pragma unroll
    for (int j = 0; j < 64; j++) {
        float s = valid ? acc[j] : 0.f;
        float q = valid ? acc[j] * acc[j] : 0.f;
#pragma unroll
        for (int o = 16; o > 0; o >>= 1) {
            s += __shfl_xor_sync(FULL, s, o);
            q += __shfl_xor_sync(FULL, q, o);
        }
        if ((t & 31) == (j & 31)) { atomicAdd(&sSum[j], s); atomicAdd(&sSq[j], q); }
    }
    __syncthreads();
    if (t < 64) {
        atomicAdd(&g_stats1[t],      sSum[t]);
        atomicAdd(&g_stats1[64 + t], sSq[t]);
    }
}

// ---------------- finalize BN1 ---------------------------------------------
__global__ void k_fin1(const float* __restrict__ g, const float* __restrict__ beta) {
    int c = threadIdx.x;
    if (c >= 64) return;
    float mu  = g_stats1[c] * (1.f / (float)VROWS);
    float var = g_stats1[64 + c] * (1.f / (float)VROWS) - mu * mu;
    float s   = g[c] * rsqrtf(var + 1e-5f);
    g_s1[c] = s;
    g_t1[c] = beta[c] - mu * s;
}

// ---------------- pass 2: recompute z1 -> h1 -> z2 (store) + BN2 stats -----
__global__ void __launch_bounds__(256) k_mlp2(const float* __restrict__ xp,
                                              const float* __restrict__ W1,
                                              const float* __restrict__ b1,
                                              const float* __restrict__ W2,
                                              const float* __restrict__ b2) {
    __shared__ float sW1[2048];
    __shared__ float sW2[4096];
    __shared__ float sS1[64], sT1[64];
    __shared__ float sSum[64], sSq[64];
    int t = threadIdx.x;
    for (int i = t; i < 2048; i += 256) sW1[i] = W1[i];
    for (int i = t; i < 4096; i += 256) sW2[i] = W2[i];
    if (t < 64) { sS1[t] = g_s1[t]; sT1[t] = g_t1[t]; sSum[t] = 0.f; sSq[t] = 0.f; }
    __syncthreads();

    int v = blockIdx.x * 256 + t;
    bool valid = v < VROWS;
    float acc[64];
#pragma unroll
    for (int j = 0; j < 64; j++) acc[j] = __ldg(b1 + j);

    if (valid) {
        const float4* xr = reinterpret_cast<const float4*>(xp + (size_t)v * 32);
        for (int ko = 0; ko < 8; ko++) {
            float4 xv = __ldg(xr + ko);
            float xs[4] = {xv.x, xv.y, xv.z, xv.w};
#pragma unroll
            for (int kk = 0; kk < 4; kk++) {
                const float4* wr =
                    reinterpret_cast<const float4*>(sW1 + (ko * 4 + kk) * 64);
#pragma unroll
                for (int jo = 0; jo < 16; jo++) {
                    float4 w = wr[jo];
                    acc[jo*4+0] += xs[kk] * w.x;
                    acc[jo*4+1] += xs[kk] * w.y;
                    acc[jo*4+2] += xs[kk] * w.z;
                    acc[jo*4+3] += xs[kk] * w.w;
                }
            }
        }
    }
    // h1 = relu(z1*s1+t1); zero for invalid rows so they contribute nothing.
#pragma unroll
    for (int j = 0; j < 64; j++)
        acc[j] = valid ? fmaxf(acc[j] * sS1[j] + sT1[j], 0.f) : 0.f;

    float* zout = g_z2 + (size_t)v * 64;
    const unsigned FULL = 0xffffffffu;

    for (int half = 0; half < 2; half++) {
        float a2[32];
#pragma unroll
        for (int j = 0; j < 32; j++) a2[j] = __ldg(b2 + half * 32 + j);
#pragma unroll
        for (int k = 0; k < 64; k++) {          // fully unrolled: acc[k] static
            float hk = acc[k];
            const float4* wr =
                reinterpret_cast<const float4*>(sW2 + k * 64 + half * 32);
#pragma unroll
            for (int jo = 0; jo < 8; jo++) {
                float4 w = wr[jo];
                a2[jo*4+0] += hk * w.x;
                a2[jo*4+1] += hk * w.y;
                a2[jo*4+2] += hk * w.z;
                a2[jo*4+3] += hk * w.w;
            }
        }
        if (valid) {
            float4* zo = reinterpret_cast<float4*>(zout + half * 32);
#pragma unroll
            for (int jo = 0; jo < 8; jo++)
                zo[jo] = make_float4(a2[jo*4+0], a2[jo*4+1], a2[jo*4+2], a2[jo*4+3]);
        }
#pragma unroll
        for (int j = 0; j < 32; j++) {
            float s = valid ? a2[j] : 0.f;
            float q = valid ? a2[j] * a2[j] : 0.f;
#pragma unroll
            for (int o = 16; o > 0; o >>= 1) {
                s += __shfl_xor_sync(FULL, s, o);
                q += __shfl_xor_sync(FULL, q, o);
            }
            if ((t & 31) == j) {
                atomicAdd(&sSum[half * 32 + j], s);
                atomicAdd(&sSq [half * 32 + j], q);
            }
        }
    }
    __syncthreads();
    if (t < 64) {
        atomicAdd(&g_stats2[t],      sSum[t]);
        atomicAdd(&g_stats2[64 + t], sSq[t]);
    }
}

// ---------------- finalize BN2 ---------------------------------------------
__global__ void k_fin2(const float* __restrict__ g, const float* __restrict__ beta) {
    int c = threadIdx.x;
    if (c >= 64) return;
    float mu  = g_stats2[c] * (1.f / (float)VROWS);
    float var = g_stats2[64 + c] * (1.f / (float)VROWS) - mu * mu;
    float s   = g[c] * rsqrtf(var + 1e-5f);
    g_s2[c] = s;
    g_t2[c] = beta[c] - mu * s;
}

// ---------------- per-segment query q = x_main@Wq + bq ---------------------
__global__ void __launch_bounds__(256) k_q(const float* __restrict__ xm,
                                           const float* __restrict__ Wq,
                                           const float* __restrict__ bq) {
    __shared__ float sW[4096];
    int t = threadIdx.x;
    for (int i = t; i < 4096; i += 256) sW[i] = Wq[i];
    __syncthreads();

    int n = blockIdx.x * 256 + t;
    if (n >= NSEG) return;
    float acc[64];
#pragma unroll
    for (int j = 0; j < 64; j++) acc[j] = __ldg(bq + j);
    const float* xr = xm + (size_t)n * 64;
    for (int k = 0; k < 64; k++) {
        float xk = __ldg(xr + k);
        const float4* wr = reinterpret_cast<const float4*>(sW + k * 64);
#pragma unroll
        for (int jo = 0; jo < 16; jo++) {
            float4 w = wr[jo];
            acc[jo*4+0] += xk * w.x;
            acc[jo*4+1] += xk * w.y;
            acc[jo*4+2] += xk * w.z;
            acc[jo*4+3] += xk * w.w;
        }
    }
    float4* qo = reinterpret_cast<float4*>(g_q + (size_t)n * 64);
#pragma unroll
    for (int jo = 0; jo < 16; jo++)
        qo[jo] = make_float4(acc[jo*4+0], acc[jo*4+1], acc[jo*4+2], acc[jo*4+3]);
}

// ---------------- P = Wk @ q (192), c = bk.q -------------------------------
__global__ void __launch_bounds__(128) k_p(const float* __restrict__ Wk,
                                           const float* __restrict__ bk) {
    __shared__ float sW[12288];          // 48 KB: Wk row-major [192,64]
    int t = threadIdx.x;
    for (int i = t; i < 12288; i += 128) sW[i] = Wk[i];
    __syncthreads();

    int n = blockIdx.x * 128 + t;
    if (n >= NSEG) return;
    const float4* qr = reinterpret_cast<const float4*>(g_q + (size_t)n * 64);
    const float4* bkr = reinterpret_cast<const float4*>(bk);

    float c = 0.f;
#pragma unroll
    for (int jo = 0; jo < 16; jo++) {
        float4 q4 = qr[jo];
        float4 b4 = __ldg(bkr + jo);
        c += q4.x * b4.x + q4.y * b4.y + q4.z * b4.z + q4.w * b4.w;
    }
    g_c[n] = c;

    for (int chunk = 0; chunk < 6; chunk++) {
        float a[32];
#pragma unroll
        for (int i = 0; i < 32; i++) a[i] = 0.f;
        for (int jo = 0; jo < 16; jo++) {
            float4 q4 = qr[jo];       // L1 hit on reload
#pragma unroll
            for (int i = 0; i < 32; i++) {
                float4 w = reinterpret_cast<const float4*>(sW)[(chunk*32 + i)*16 + jo];
                a[i] += q4.x * w.x + q4.y * w.y + q4.z * w.z + q4.w * w.w;
            }
        }
        if (chunk < 2) {
#pragma unroll
            for (int i = 0; i < 32; i++) g_Pt[(size_t)n * 64 + chunk * 32 + i] = a[i];
        } else {
#pragma unroll
            for (int i = 0; i < 32; i++) g_Pb[(size_t)n * 128 + (chunk-2)*32 + i] = a[i];
        }
    }
}

// ---------------- warp-per-segment: scores, softmax, pool, gate ------------
__global__ void __launch_bounds__(256) k_seg(const float* __restrict__ x_mod,
                                             const int* __restrict__ csr,
                                             float* __restrict__ out,
                                             float* __restrict__ seen) {
    int gw = (blockIdx.x * blockDim.x + threadIdx.x) >> 5;
    int l  = threadIdx.x & 31;
    if (gw >= NSEG) return;
    int r0 = csr[gw], r1 = csr[gw + 1];
    int cnt = r1 - r0;
    float* op = out + (size_t)gw * 128;
    if (cnt <= 0) {
#pragma unroll
        for (int k = 0; k < 4; k++) op[l + 32 * k] = 0.f;
        if (seen && l == 0) seen[gw] = 0.f;
        return;
    }
    float pt0 = g_Pt[(size_t)gw*64 + l],       pt1 = g_Pt[(size_t)gw*64 + 32 + l];
    float pb0 = g_Pb[(size_t)gw*128 + l],      pb1 = g_Pb[(size_t)gw*128 + 32 + l];
    float pb2 = g_Pb[(size_t)gw*128 + 64 + l], pb3 = g_Pb[(size_t)gw*128 + 96 + l];
    float cc  = g_c[gw];
    float s2a = g_s2[l], s2b = g_s2[32 + l];
    float t2a = g_t2[l], t2b = g_t2[32 + l];
    float inv = rsqrtf((float)cnt);

    float m = -INFINITY, d = 0.f;
    const unsigned FULL = 0xffffffffu;
    for (int v = r0; v < r1; v++) {
        const float* zr = g_z2 + (size_t)v * 64;
        float ha = fmaxf(zr[l]      * s2a + t2a, 0.f);
        float hb = fmaxf(zr[32 + l] * s2b + t2b, 0.f);
        const float* xr = x_mod + (size_t)v * 128;
        float part = ha * pt0 + hb * pt1
                   + xr[l]      * pb0 + xr[32 + l] * pb1
                   + xr[64 + l] * pb2 + xr[96 + l] * pb3;
#pragma unroll
        for (int o = 16; o > 0; o >>= 1) part += __shfl_xor_sync(FULL, part, o);
        float X = part + cc;
        if (l == 0) g_X[v] = X;
        if (X > m) { d = d * __expf((m - X) * inv) + 1.f; m = X; }
        else       { d += __expf((X - m) * inv); }
    }
    __threadfence_block();
    __syncwarp();

    float dn = d + 1e-12f;
    float G  = tanhf(fmaxf(m, 0.f));
    float p0 = -INFINITY, p1 = -INFINITY, p2 = -INFINITY, p3 = -INFINITY;
    for (int v = r0; v < r1; v++) {
        float a = __expf((g_X[v] - m) * inv) / dn;   // plain load: coherent path
        const float* xr = x_mod + (size_t)v * 128;
        p0 = fmaxf(p0, xr[l]      * a);
        p1 = fmaxf(p1, xr[32 + l] * a);
        p2 = fmaxf(p2, xr[64 + l] * a);
        p3 = fmaxf(p3, xr[96 + l] * a);
    }
    op[l]      = p0 * G;
    op[32 + l] = p1 * G;
    op[64 + l] = p2 * G;
    op[96 + l] = p3 * G;
    if (seen && l == 0) seen[gw] = 1.f;
}

// ---------------- launch ----------------------------------------------------
extern "C" void kernel_launch(void* const* d_in, const int* in_sizes, int n_in,
                              void* d_out, int out_size) {
    const float* x_main = (const float*)d_in[0];
    const float* x_mod  = (const float*)d_in[1];
    const float* x_proj = (const float*)d_in[2];
    const int*   csr    = (const int*)  d_in[3];
    const float* Wq     = (const float*)d_in[4];
    const float* bq     = (const float*)d_in[5];
    const float* W1     = (const float*)d_in[6];
    const float* b1     = (const float*)d_in[7];
    const float* g1     = (const float*)d_in[8];
    const float* beta1  = (const float*)d_in[9];
    const float* W2     = (const float*)d_in[10];
    const float* b2     = (const float*)d_in[11];
    const float* g2     = (const float*)d_in[12];
    const float* beta2  = (const float*)d_in[13];
    const float* Wk     = (const float*)d_in[14];
    const float* bk     = (const float*)d_in[15];

    float* out  = (float*)d_out;
    float* seen = (out_size >= NSEG * 129) ? out + (size_t)NSEG * 128 : nullptr;

    k_init  <<<1, 128>>>();
    k_stats1<<<(VROWS + 255) / 256, 256>>>(x_proj, W1, b1);
    k_fin1  <<<1, 64>>>(g1, beta1);
    k_mlp2  <<<(VROWS + 255) / 256, 256>>>(x_proj, W1, b1, W2, b2);
    k_fin2  <<<1, 64>>>(g2, beta2);
    k_q     <<<(NSEG + 255) / 256, 256>>>(x_main, Wq, bq);
    k_p     <<<(NSEG + 127) / 128, 128>>>(Wk, bk);
    k_seg   <<<(NSEG + 7) / 8, 256>>>(x_mod, csr, out, seen);
}

// round 4
// speedup vs baseline: 1.5204x; 1.5204x over previous
#include <cuda_runtime.h>
#include <math.h>

#define NSEG  125000
#define VROWS 1000000

typedef unsigned long long u64;

// ---------------- packed f32x2 helpers (sm_100+) ----------------------------
__device__ __forceinline__ u64 pack2(float x) {
    u64 r; unsigned xi = __float_as_uint(x);
    asm("mov.b64 %0, {%1, %1};" : "=l"(r) : "r"(xi));
    return r;
}
__device__ __forceinline__ void unpack2(u64 v, float& a, float& b) {
    unsigned lo, hi;
    asm("mov.b64 {%0, %1}, %2;" : "=r"(lo), "=r"(hi) : "l"(v));
    a = __uint_as_float(lo); b = __uint_as_float(hi);
}
__device__ __forceinline__ void ffma2(u64& acc, u64 a, u64 b) {
    asm("fma.rn.f32x2 %0, %1, %2, %0;" : "+l"(acc) : "l"(a), "l"(b));
}

// Reduce 64 per-lane channels across a warp. On return lane l holds
// channel sums {2l, 2l+1} in v[0], v[1].
__device__ __forceinline__ void wreduce64(float* v) {
    const unsigned FULL = 0xffffffffu;
    int l = threadIdx.x & 31;
#pragma unroll
    for (int o = 16; o > 0; o >>= 1) {
#pragma unroll
        for (int j = 0; j < 2 * o; j++) {
            float lo = v[j], hi = v[j + 2 * o];
            float send = (l & o) ? lo : hi;
            float got  = __shfl_xor_sync(FULL, send, o);
            v[j] = ((l & o) ? hi : lo) + got;
        }
    }
}

// ---------------- scratch (device globals; no allocation allowed) ----------
static __device__ float g_z2[(size_t)VROWS * 64];   // z2 pre-BN activations
static __device__ float g_q [(size_t)NSEG * 64];    // per-segment query
static __device__ float g_Pt[(size_t)NSEG * 64];    // Wk_top @ q   (h2 part)
static __device__ float g_Pb[(size_t)NSEG * 128];   // Wk_bot @ q   (x_mod part)
static __device__ float g_c [NSEG];                 // bk . q
static __device__ float g_X [VROWS];                // per-row scores
static __device__ float g_stats1[128];              // sum(64) | sumsq(64)
static __device__ float g_stats2[128];
static __device__ float g_s1[64], g_t1[64], g_s2[64], g_t2[64];

// ---------------- init: zero the stat accumulators -------------------------
__global__ void k_init() {
    int t = threadIdx.x;
    if (t < 128) { g_stats1[t] = 0.f; g_stats2[t] = 0.f; }
}

// ---------------- pass 1: z1 = x_proj@W1+b1, accumulate BN1 stats ----------
// block = 128 threads = 128 rows; x staged coalesced through shared.
__global__ void __launch_bounds__(128) k_stats1(const float* __restrict__ xp,
                                                const float* __restrict__ W1,
                                                const float* __restrict__ b1) {
    __shared__ __align__(16) float sX[128 * 33];   // pad 33: conflict-free scalar reads
    __shared__ __align__(16) float sW[2048];       // 32x64
    __shared__ float sSum[64], sSq[64];
    int t = threadIdx.x;
    int base = blockIdx.x * 128;
    int nrows = min(128, VROWS - base);

    for (int i = t; i < 512; i += 128)
        ((float4*)sW)[i] = ((const float4*)W1)[i];
    if (t < 64) { sSum[t] = 0.f; sSq[t] = 0.f; }
    const float4* xg = (const float4*)(xp + (size_t)base * 32);
    for (int i = t; i < nrows * 8; i += 128) {
        float4 v = xg[i];
        int r = i >> 3, c = (i & 7) << 2;
        float* d = &sX[r * 33 + c];
        d[0] = v.x; d[1] = v.y; d[2] = v.z; d[3] = v.w;
    }
    __syncthreads();

    bool valid = t < nrows;
    u64 acc[32];
    const u64* b1p = (const u64*)b1;
#pragma unroll
    for (int j = 0; j < 32; j++) acc[j] = b1p[j];

    if (valid) {
#pragma unroll 8
        for (int k = 0; k < 32; k++) {
            u64 xx = pack2(sX[t * 33 + k]);
            const ulonglong2* wr = (const ulonglong2*)(sW + k * 64);
#pragma unroll
            for (int jo = 0; jo < 16; jo++) {
                ulonglong2 w = wr[jo];
                ffma2(acc[2 * jo],     xx, w.x);
                ffma2(acc[2 * jo + 1], xx, w.y);
            }
        }
    }

    float s[64], q[64];
#pragma unroll
    for (int j = 0; j < 32; j++) {
        float a, b; unpack2(acc[j], a, b);
        if (!valid) { a = 0.f; b = 0.f; }
        s[2 * j] = a;     s[2 * j + 1] = b;
        q[2 * j] = a * a; q[2 * j + 1] = b * b;
    }
    wreduce64(s);
    wreduce64(q);
    int l = t & 31;
    atomicAdd(&sSum[2 * l],     s[0]);
    atomicAdd(&sSum[2 * l + 1], s[1]);
    atomicAdd(&sSq [2 * l],     q[0]);
    atomicAdd(&sSq [2 * l + 1], q[1]);
    __syncthreads();
    if (t < 64) {
        atomicAdd(&g_stats1[t],      sSum[t]);
        atomicAdd(&g_stats1[64 + t], sSq[t]);
    }
}

// ---------------- finalize BN1 ---------------------------------------------
__global__ void k_fin1(const float* __restrict__ g, const float* __restrict__ beta) {
    int c = threadIdx.x;
    if (c >= 64) return;
    float mu  = g_stats1[c] * (1.f / (float)VROWS);
    float var = g_stats1[64 + c] * (1.f / (float)VROWS) - mu * mu;
    float s   = g[c] * rsqrtf(var + 1e-5f);
    g_s1[c] = s;
    g_t1[c] = beta[c] - mu * s;
}

// ---------------- pass 2: recompute z1 -> h1 -> z2 (store) + BN2 stats -----
// block = 128 threads = 128 rows; x staged in, z2 staged out (coalesced).
__global__ void __launch_bounds__(128) k_mlp2(const float* __restrict__ xp,
                                              const float* __restrict__ W1,
                                              const float* __restrict__ b1,
                                              const float* __restrict__ W2,
                                              const float* __restrict__ b2) {
    __shared__ __align__(16) float sX[128 * 36];   // pad 36: 16B-aligned rows (z2 stage reuse)
    __shared__ __align__(16) float sW[4096];       // W1 (8KB) then W2 (16KB)
    __shared__ float sS1[64], sT1[64], sSum[64], sSq[64];
    int t = threadIdx.x;
    int base = blockIdx.x * 128;
    int nrows = min(128, VROWS - base);

    for (int i = t; i < 512; i += 128)
        ((float4*)sW)[i] = ((const float4*)W1)[i];
    if (t < 64) { sS1[t] = g_s1[t]; sT1[t] = g_t1[t]; sSum[t] = 0.f; sSq[t] = 0.f; }
    const float4* xg = (const float4*)(xp + (size_t)base * 32);
    for (int i = t; i < nrows * 8; i += 128) {
        float4 v = xg[i];
        int r = i >> 3, c = (i & 7) << 2;
        float* d = &sX[r * 36 + c];
        d[0] = v.x; d[1] = v.y; d[2] = v.z; d[3] = v.w;
    }
    __syncthreads();

    bool valid = t < nrows;
    u64 acc[32];
    const u64* b1p = (const u64*)b1;
#pragma unroll
    for (int j = 0; j < 32; j++) acc[j] = b1p[j];

    if (valid) {
#pragma unroll 8
        for (int k = 0; k < 32; k++) {
            u64 xx = pack2(sX[t * 36 + k]);
            const ulonglong2* wr = (const ulonglong2*)(sW + k * 64);
#pragma unroll
            for (int jo = 0; jo < 16; jo++) {
                ulonglong2 w = wr[jo];
                ffma2(acc[2 * jo],     xx, w.x);
                ffma2(acc[2 * jo + 1], xx, w.y);
            }
        }
    }

    // h1 = relu(z1*s1+t1); zero for invalid rows
    float h[64];
#pragma unroll
    for (int j = 0; j < 32; j++) {
        float a, b; unpack2(acc[j], a, b);
        h[2 * j]     = valid ? fmaxf(a * sS1[2 * j]     + sT1[2 * j],     0.f) : 0.f;
        h[2 * j + 1] = valid ? fmaxf(b * sS1[2 * j + 1] + sT1[2 * j + 1], 0.f) : 0.f;
    }

    __syncthreads();                         // done with W1 region
    for (int i = t; i < 1024; i += 128)      // load W2 (L2-resident across blocks)
        ((float4*)sW)[i] = ((const float4*)W2)[i];
    __syncthreads();

    const u64* b2p = (const u64*)b2;
#pragma unroll
    for (int j = 0; j < 32; j++) acc[j] = b2p[j];
#pragma unroll
    for (int k = 0; k < 64; k++) {           // FULL unroll: h[k] must stay in regs
        u64 hh = pack2(h[k]);
        const ulonglong2* wr = (const ulonglong2*)(sW + k * 64);
#pragma unroll
        for (int jo = 0; jo < 16; jo++) {
            ulonglong2 w = wr[jo];
            ffma2(acc[2 * jo],     hh, w.x);
            ffma2(acc[2 * jo + 1], hh, w.y);
        }
    }

    // unpack z2 (zero for invalid rows — also feeds stats)
    float z[64];
#pragma unroll
    for (int j = 0; j < 32; j++) {
        float a, b; unpack2(acc[j], a, b);
        z[2 * j]     = valid ? a : 0.f;
        z[2 * j + 1] = valid ? b : 0.f;
    }

    // staged coalesced z2 store, two 32-col halves through sX
#pragma unroll
    for (int half = 0; half < 2; half++) {
        __syncthreads();
        if (valid) {
            float4* zr = (float4*)&sX[t * 36];
#pragma unroll
            for (int jo = 0; jo < 8; jo++)
                zr[jo] = make_float4(z[half * 32 + 4 * jo],     z[half * 32 + 4 * jo + 1],
                                     z[half * 32 + 4 * jo + 2], z[half * 32 + 4 * jo + 3]);
        }
        __syncthreads();
        float* zg = g_z2 + (size_t)base * 64 + half * 32;
        for (int i = t; i < nrows * 8; i += 128) {
            int r = i >> 3, c = (i & 7) << 2;
            float4 v = *(const float4*)&sX[r * 36 + c];
            *(float4*)&zg[(size_t)r * 64 + c] = v;
        }
    }

    // BN2 stats
    float q[64];
#pragma unroll
    for (int j = 0; j < 64; j++) q[j] = z[j] * z[j];
    wreduce64(z);
    wreduce64(q);
    int l = t & 31;
    atomicAdd(&sSum[2 * l],     z[0]);
    atomicAdd(&sSum[2 * l + 1], z[1]);
    atomicAdd(&sSq [2 * l],     q[0]);
    atomicAdd(&sSq [2 * l + 1], q[1]);
    __syncthreads();
    if (t < 64) {
        atomicAdd(&g_stats2[t],      sSum[t]);
        atomicAdd(&g_stats2[64 + t], sSq[t]);
    }
}

// ---------------- finalize BN2 ---------------------------------------------
__global__ void k_fin2(const float* __restrict__ g, const float* __restrict__ beta) {
    int c = threadIdx.x;
    if (c >= 64) return;
    float mu  = g_stats2[c] * (1.f / (float)VROWS);
    float var = g_stats2[64 + c] * (1.f / (float)VROWS) - mu * mu;
    float s   = g[c] * rsqrtf(var + 1e-5f);
    g_s2[c] = s;
    g_t2[c] = beta[c] - mu * s;
}

// ---------------- per-segment query q = x_main@Wq + bq ---------------------
// block = 64 threads = 64 rows; x_main staged coalesced.
__global__ void __launch_bounds__(64) k_q(const float* __restrict__ xm,
                                          const float* __restrict__ Wq,
                                          const float* __restrict__ bq) {
    __shared__ __align__(16) float sX[64 * 65];    // pad 65: conflict-free scalar reads
    __shared__ __align__(16) float sW[4096];
    int t = threadIdx.x;
    int base = blockIdx.x * 64;
    int nrows = min(64, NSEG - base);

    for (int i = t; i < 1024; i += 64)
        ((float4*)sW)[i] = ((const float4*)Wq)[i];
    const float4* xg = (const float4*)(xm + (size_t)base * 64);
    for (int i = t; i < nrows * 16; i += 64) {
        float4 v = xg[i];
        int r = i >> 4, c = (i & 15) << 2;
        float* d = &sX[r * 65 + c];
        d[0] = v.x; d[1] = v.y; d[2] = v.z; d[3] = v.w;
    }
    __syncthreads();

    if (t >= nrows) return;
    int n = base + t;
    u64 acc[32];
    const u64* bp = (const u64*)bq;
#pragma unroll
    for (int j = 0; j < 32; j++) acc[j] = bp[j];
#pragma unroll 8
    for (int k = 0; k < 64; k++) {
        u64 xx = pack2(sX[t * 65 + k]);
        const ulonglong2* wr = (const ulonglong2*)(sW + k * 64);
#pragma unroll
        for (int jo = 0; jo < 16; jo++) {
            ulonglong2 w = wr[jo];
            ffma2(acc[2 * jo],     xx, w.x);
            ffma2(acc[2 * jo + 1], xx, w.y);
        }
    }
    ulonglong2* qo = (ulonglong2*)(g_q + (size_t)n * 64);
#pragma unroll
    for (int jo = 0; jo < 16; jo++)
        qo[jo] = make_ulonglong2(acc[2 * jo], acc[2 * jo + 1]);
}

// ---------------- P = Wk @ q (192), c = bk.q -------------------------------
__global__ void __launch_bounds__(128) k_p(const float* __restrict__ Wk,
                                           const float* __restrict__ bk) {
    __shared__ float sW[12288];          // 48 KB: Wk row-major [192,64]
    int t = threadIdx.x;
    for (int i = t; i < 12288; i += 128) sW[i] = Wk[i];
    __syncthreads();

    int n = blockIdx.x * 128 + t;
    if (n >= NSEG) return;
    const float4* qr = reinterpret_cast<const float4*>(g_q + (size_t)n * 64);
    const float4* bkr = reinterpret_cast<const float4*>(bk);

    float c = 0.f;
#pragma unroll
    for (int jo = 0; jo < 16; jo++) {
        float4 q4 = qr[jo];
        float4 b4 = __ldg(bkr + jo);
        c += q4.x * b4.x + q4.y * b4.y + q4.z * b4.z + q4.w * b4.w;
    }
    g_c[n] = c;

    for (int chunk = 0; chunk < 6; chunk++) {
        float a[32];
#pragma unroll
        for (int i = 0; i < 32; i++) a[i] = 0.f;
        for (int jo = 0; jo < 16; jo++) {
            float4 q4 = qr[jo];       // L1 hit on reload
#pragma unroll
            for (int i = 0; i < 32; i++) {
                float4 w = reinterpret_cast<const float4*>(sW)[(chunk*32 + i)*16 + jo];
                a[i] += q4.x * w.x + q4.y * w.y + q4.z * w.z + q4.w * w.w;
            }
        }
        if (chunk < 2) {
#pragma unroll
            for (int i = 0; i < 32; i++) g_Pt[(size_t)n * 64 + chunk * 32 + i] = a[i];
        } else {
#pragma unroll
            for (int i = 0; i < 32; i++) g_Pb[(size_t)n * 128 + (chunk-2)*32 + i] = a[i];
        }
    }
}

// ---------------- warp-per-segment: scores, softmax, pool, gate ------------
__global__ void __launch_bounds__(256) k_seg(const float* __restrict__ x_mod,
                                             const int* __restrict__ csr,
                                             float* __restrict__ out,
                                             float* __restrict__ seen) {
    int gw = (blockIdx.x * blockDim.x + threadIdx.x) >> 5;
    int l  = threadIdx.x & 31;
    if (gw >= NSEG) return;
    int r0 = csr[gw], r1 = csr[gw + 1];
    int cnt = r1 - r0;
    float* op = out + (size_t)gw * 128;
    if (cnt <= 0) {
#pragma unroll
        for (int k = 0; k < 4; k++) op[l + 32 * k] = 0.f;
        if (seen && l == 0) seen[gw] = 0.f;
        return;
    }
    float pt0 = g_Pt[(size_t)gw*64 + l],       pt1 = g_Pt[(size_t)gw*64 + 32 + l];
    float pb0 = g_Pb[(size_t)gw*128 + l],      pb1 = g_Pb[(size_t)gw*128 + 32 + l];
    float pb2 = g_Pb[(size_t)gw*128 + 64 + l], pb3 = g_Pb[(size_t)gw*128 + 96 + l];
    float cc  = g_c[gw];
    float s2a = g_s2[l], s2b = g_s2[32 + l];
    float t2a = g_t2[l], t2b = g_t2[32 + l];
    float inv = rsqrtf((float)cnt);

    float m = -INFINITY, d = 0.f;
    const unsigned FULL = 0xffffffffu;
    for (int v = r0; v < r1; v++) {
        const float* zr = g_z2 + (size_t)v * 64;
        float ha = fmaxf(zr[l]      * s2a + t2a, 0.f);
        float hb = fmaxf(zr[32 + l] * s2b + t2b, 0.f);
        const float* xr = x_mod + (size_t)v * 128;
        float part = ha * pt0 + hb * pt1
                   + xr[l]      * pb0 + xr[32 + l] * pb1
                   + xr[64 + l] * pb2 + xr[96 + l] * pb3;
#pragma unroll
        for (int o = 16; o > 0; o >>= 1) part += __shfl_xor_sync(FULL, part, o);
        float X = part + cc;
        if (l == 0) g_X[v] = X;
        if (X > m) { d = d * __expf((m - X) * inv) + 1.f; m = X; }
        else       { d += __expf((X - m) * inv); }
    }
    __threadfence_block();
    __syncwarp();

    float dn = d + 1e-12f;
    float G  = tanhf(fmaxf(m, 0.f));
    float p0 = -INFINITY, p1 = -INFINITY, p2 = -INFINITY, p3 = -INFINITY;
    for (int v = r0; v < r1; v++) {
        float a = __expf((g_X[v] - m) * inv) / dn;
        const float* xr = x_mod + (size_t)v * 128;
        p0 = fmaxf(p0, xr[l]      * a);
        p1 = fmaxf(p1, xr[32 + l] * a);
        p2 = fmaxf(p2, xr[64 + l] * a);
        p3 = fmaxf(p3, xr[96 + l] * a);
    }
    op[l]      = p0 * G;
    op[32 + l] = p1 * G;
    op[64 + l] = p2 * G;
    op[96 + l] = p3 * G;
    if (seen && l == 0) seen[gw] = 1.f;
}

// ---------------- launch ----------------------------------------------------
extern "C" void kernel_launch(void* const* d_in, const int* in_sizes, int n_in,
                              void* d_out, int out_size) {
    const float* x_main = (const float*)d_in[0];
    const float* x_mod  = (const float*)d_in[1];
    const float* x_proj = (const float*)d_in[2];
    const int*   csr    = (const int*)  d_in[3];
    const float* Wq     = (const float*)d_in[4];
    const float* bq     = (const float*)d_in[5];
    const float* W1     = (const float*)d_in[6];
    const float* b1     = (const float*)d_in[7];
    const float* g1     = (const float*)d_in[8];
    const float* beta1  = (const float*)d_in[9];
    const float* W2     = (const float*)d_in[10];
    const float* b2     = (const float*)d_in[11];
    const float* g2     = (const float*)d_in[12];
    const float* beta2  = (const float*)d_in[13];
    const float* Wk     = (const float*)d_in[14];
    const float* bk     = (const float*)d_in[15];

    float* out  = (float*)d_out;
    float* seen = (out_size >= NSEG * 129) ? out + (size_t)NSEG * 128 : nullptr;

    k_init  <<<1, 128>>>();
    k_stats1<<<(VROWS + 127) / 128, 128>>>(x_proj, W1, b1);
    k_fin1  <<<1, 64>>>(g1, beta1);
    k_mlp2  <<<(VROWS + 127) / 128, 128>>>(x_proj, W1, b1, W2, b2);
    k_fin2  <<<1, 64>>>(g2, beta2);
    k_q     <<<(NSEG + 63) / 64, 64>>>(x_main, Wq, bq);
    k_p     <<<(NSEG + 127) / 128, 128>>>(Wk, bk);
    k_seg   <<<(NSEG + 7) / 8, 256>>>(x_mod, csr, out, seen);
}